// round 6
// baseline (speedup 1.0000x reference)
#include <cuda_runtime.h>
#include <cstdint>

#define BB 256
#define TT 512
#define IND 64
#define HH 512
#define GG 2048   // 4*H
#define NCTA 128

// ---------------- device scratch ----------------
__device__ float g_xproj[(size_t)TT * BB * GG];
__device__ float g_hseq [(size_t)TT * BB * HH];
__device__ float g_hbuf [2][BB * HH];
__device__ float g_Whh  [2][GG * HH];     // gate-interleaved rows, tf32-rounded
__device__ float g_Wih0 [GG * IND];
__device__ float g_Wih1 [GG * HH];
__device__ float g_bias [2][GG];
__device__ unsigned g_cnt[2][4][4];       // [layer][batch-tile][k-chunk] monotonic counters

// ---------------- helpers ----------------
__device__ __forceinline__ float tf32f(float x) {
    uint32_t u;
    asm("cvt.rna.tf32.f32 %0, %1;" : "=r"(u) : "f"(x));
    return __uint_as_float(u);
}

// pair-fragment mma: thread q supplies k-lanes (q, q+4); we feed it the
// adjacent pair (k0+2q, k0+2q+1) from BOTH operands -> dot product unchanged.
__device__ __forceinline__ void mma_tf32(float* c,
                                         float a0, float a1, float a2, float a3,
                                         float b0, float b1) {
    asm volatile(
        "mma.sync.aligned.m16n8k8.row.col.f32.tf32.tf32.f32 "
        "{%0,%1,%2,%3}, {%4,%5,%6,%7}, {%8,%9}, {%0,%1,%2,%3};\n"
        : "+f"(c[0]), "+f"(c[1]), "+f"(c[2]), "+f"(c[3])
        : "r"(__float_as_uint(a0)), "r"(__float_as_uint(a1)),
          "r"(__float_as_uint(a2)), "r"(__float_as_uint(a3)),
          "r"(__float_as_uint(b0)), "r"(__float_as_uint(b1)));
}

__device__ __forceinline__ float fsigm(float x) {
    return __fdividef(1.0f, 1.0f + __expf(-x));
}
__device__ __forceinline__ float ftanh(float x) {
    return 2.0f * __fdividef(1.0f, 1.0f + __expf(-2.0f * x)) - 1.0f;
}

__device__ __forceinline__ void cpasync16(uint32_t saddr, const void* g) {
    asm volatile("cp.async.cg.shared.global [%0], [%1], 16;\n" :: "r"(saddr), "l"(g));
}
__device__ __forceinline__ void cpasync_commit() {
    asm volatile("cp.async.commit_group;\n");
}
template <int N> __device__ __forceinline__ void cpasync_wait() {
    asm volatile("cp.async.wait_group %0;\n" :: "n"(N) : "memory");
}

__device__ __forceinline__ unsigned ld_acq(const unsigned* p) {
    unsigned v;
    asm volatile("ld.acquire.gpu.global.u32 %0, [%1];" : "=r"(v) : "l"(p) : "memory");
    return v;
}

__device__ __forceinline__ void wait_cnt(const unsigned* p, unsigned thr) {
    if (ld_acq(p) >= thr) return;
    while (ld_acq(p) < thr) __nanosleep(32);
}

// ---------------- weight permute (gate interleave) + tf32 pre-round ----------------
__global__ void prep_kernel(const float* __restrict__ Wih0, const float* __restrict__ Whh0,
                            const float* __restrict__ bih0, const float* __restrict__ bhh0,
                            const float* __restrict__ Wih1, const float* __restrict__ Whh1,
                            const float* __restrict__ bih1, const float* __restrict__ bhh1) {
    int stride = gridDim.x * blockDim.x;
    int tid = blockIdx.x * blockDim.x + threadIdx.x;
    if (blockIdx.x == 0 && threadIdx.x < 32) {
        ((unsigned*)g_cnt)[threadIdx.x] = 0u;   // reset counters every replay
    }
    for (int i = tid; i < GG * HH; i += stride) {
        int orow = i / HH, k = i - orow * HH;
        int j = orow >> 2, gate = orow & 3;
        int src = (gate * HH + j) * HH + k;
        g_Whh[0][i] = tf32f(Whh0[src]);
        g_Whh[1][i] = tf32f(Whh1[src]);
        g_Wih1[i]   = tf32f(Wih1[src]);
    }
    for (int i = tid; i < GG * IND; i += stride) {
        int orow = i / IND, k = i - orow * IND;
        int j = orow >> 2, gate = orow & 3;
        g_Wih0[i] = tf32f(Wih0[(gate * HH + j) * IND + k]);
    }
    for (int i = tid; i < GG; i += stride) {
        int j = i >> 2, gate = i & 3;
        int src = gate * HH + j;
        g_bias[0][i] = bih0[src] + bhh0[src];
        g_bias[1][i] = bih1[src] + bhh1[src];
    }
}

// ---------------- layer-0 input projection (K=64) ----------------
#define KC 64
__global__ void __launch_bounds__(256)
inproj0_kernel(const float* __restrict__ x) {
    __shared__ float sA[64][KC + 4];
    __shared__ float sB[64][KC + 4];

    const float* __restrict__ W    = g_Wih0;
    const float* __restrict__ bias = g_bias[0];

    int tid = threadIdx.x;
    int m0 = blockIdx.x * 64;
    int n0 = blockIdx.y * 64;
    int t  = m0 >> 8;
    int b0 = m0 & 255;
    const float* Abase = x + (size_t)b0 * TT * IND + (size_t)t * IND;

    int w = tid >> 5, lane = tid & 31, q = lane & 3, gq = lane >> 2;
    int wm = w & 3, wn = w >> 2;

    float acc[4][4] = {};

#pragma unroll
    for (int r = 0; r < 4; r++) {
        int idx = tid + r * 256;
        int row = idx >> 4;
        int c4  = idx & 15;
        float4 v = *reinterpret_cast<const float4*>(Abase + (size_t)row * TT * IND + c4 * 4);
        v.x = tf32f(v.x); v.y = tf32f(v.y); v.z = tf32f(v.z); v.w = tf32f(v.w);
        *reinterpret_cast<float4*>(&sA[row][c4 * 4]) = v;
        float4 wv = *reinterpret_cast<const float4*>(W + (long)(n0 + row) * IND + c4 * 4);
        *reinterpret_cast<float4*>(&sB[row][c4 * 4]) = wv;
    }
    __syncthreads();
#pragma unroll
    for (int ks = 0; ks < KC / 8; ks++) {
        int k0 = ks * 8;
        float a0 = sA[wm * 16 + gq    ][k0 + q];
        float a1 = sA[wm * 16 + gq + 8][k0 + q];
        float a2 = sA[wm * 16 + gq    ][k0 + q + 4];
        float a3 = sA[wm * 16 + gq + 8][k0 + q + 4];
#pragma unroll
        for (int nt = 0; nt < 4; nt++) {
            int n = wn * 32 + nt * 8 + gq;
            mma_tf32(acc[nt], a0, a1, a2, a3, sB[n][k0 + q], sB[n][k0 + q + 4]);
        }
    }

#pragma unroll
    for (int nt = 0; nt < 4; nt++) {
        int col = n0 + wn * 32 + nt * 8 + q * 2;
        float bv0 = bias[col], bv1 = bias[col + 1];
        int row = m0 + wm * 16 + gq;
        *reinterpret_cast<float2*>(g_xproj + (size_t)row * GG + col) =
            make_float2(acc[nt][0] + bv0, acc[nt][1] + bv1);
        *reinterpret_cast<float2*>(g_xproj + (size_t)(row + 8) * GG + col) =
            make_float2(acc[nt][2] + bv0, acc[nt][3] + bv1);
    }
}

// ---------------- layer-1 input projection: 128x128 CTA, 64x32 warps ----------------
#define IP_APAD 72
#define IP_TILEF (128 * IP_APAD)
#define IP2_SMEM (4 * IP_TILEF * 4)

__global__ void __launch_bounds__(256, 1)
inproj2_kernel() {
    extern __shared__ float sm[];
    float* sA[2] = { sm,                sm + IP_TILEF };
    float* sB[2] = { sm + 2 * IP_TILEF, sm + 3 * IP_TILEF };
    uint32_t sAu[2], sBu[2];
#pragma unroll
    for (int i = 0; i < 2; i++) {
        sAu[i] = (uint32_t)__cvta_generic_to_shared(sA[i]);
        sBu[i] = (uint32_t)__cvta_generic_to_shared(sB[i]);
    }

    int tid = threadIdx.x, w = tid >> 5, lane = tid & 31, q = lane & 3, gq = lane >> 2;
    int wm = w & 1, wn = w >> 1;
    int n0 = blockIdx.x * 128;
    long m0 = (long)blockIdx.y * 128;
    const float* Ab = g_hseq + m0 * HH;
    const float* Bb = g_Wih1 + (long)n0 * HH;

    float acc[4][4][4] = {};

#pragma unroll
    for (int r = 0; r < 8; r++) {
        int idx = tid + r * 256;
        int row = idx >> 4, c4 = idx & 15;
        cpasync16(sAu[0] + (row * IP_APAD + c4 * 4) * 4, Ab + (long)row * HH + c4 * 4);
        cpasync16(sBu[0] + (row * IP_APAD + c4 * 4) * 4, Bb + (long)row * HH + c4 * 4);
    }
    cpasync_commit();

    for (int ch = 0; ch < 8; ch++) {
        cpasync_wait<0>();
        __syncthreads();
        if (ch < 7) {
            int bi = (ch + 1) & 1;
#pragma unroll
            for (int r = 0; r < 8; r++) {
                int idx = tid + r * 256;
                int row = idx >> 4, c4 = idx & 15;
                cpasync16(sAu[bi] + (row * IP_APAD + c4 * 4) * 4,
                          Ab + (long)row * HH + (ch + 1) * 64 + c4 * 4);
                cpasync16(sBu[bi] + (row * IP_APAD + c4 * 4) * 4,
                          Bb + (long)row * HH + (ch + 1) * 64 + c4 * 4);
            }
            cpasync_commit();
        }
        const float* cA = sA[ch & 1] + (wm * 64) * IP_APAD;
        const float* cB = sB[ch & 1] + (wn * 32) * IP_APAD;
#pragma unroll
        for (int ks = 0; ks < 8; ks++) {
            int k2 = ks * 8 + 2 * q;
            float2 aL[4], aH[4];
#pragma unroll
            for (int mt = 0; mt < 4; mt++) {
                aL[mt] = *reinterpret_cast<const float2*>(cA + (mt * 16 + gq    ) * IP_APAD + k2);
                aH[mt] = *reinterpret_cast<const float2*>(cA + (mt * 16 + gq + 8) * IP_APAD + k2);
            }
#pragma unroll
            for (int nt = 0; nt < 4; nt++) {
                float2 bf = *reinterpret_cast<const float2*>(cB + (nt * 8 + gq) * IP_APAD + k2);
#pragma unroll
                for (int mt = 0; mt < 4; mt++)
                    mma_tf32(acc[mt][nt], aL[mt].x, aH[mt].x, aL[mt].y, aH[mt].y, bf.x, bf.y);
            }
        }
    }

#pragma unroll
    for (int nt = 0; nt < 4; nt++) {
        int col = n0 + wn * 32 + nt * 8 + q * 2;
        float bv0 = g_bias[1][col], bv1 = g_bias[1][col + 1];
#pragma unroll
        for (int mt = 0; mt < 4; mt++) {
            long row = m0 + wm * 64 + mt * 16 + gq;
            *reinterpret_cast<float2*>(g_xproj + row * GG + col) =
                make_float2(acc[mt][nt][0] + bv0, acc[mt][nt][1] + bv1);
            *reinterpret_cast<float2*>(g_xproj + (row + 8) * GG + col) =
                make_float2(acc[mt][nt][2] + bv0, acc[mt][nt][3] + bv1);
        }
    }
}

// ---------------- persistent LSTM scan with fine-grained producer/consumer sync ----------------
// CTA (bi, ni): batch tile b0=64*bi, gate-column tile n0=64*ni (hidden j0=16*ni).
// Counters: g_cnt[L][bi][g] incremented by the 8 CTAs with ni in [8g, 8g+8);
// init counts as the first signal, so consumer threshold for step t is 8*(t+1).
#define WPAD 520
#define APAD 136
#define SW_F (64 * WPAD)
#define SA_F (64 * APAD)
#define SMEM_SCAN ((SW_F + 2 * SA_F) * 4)

template <int LAYER>
__global__ void __launch_bounds__(128, 1)
scan_kernel() {
    extern __shared__ float sm[];
    float* sW  = sm;
    float* sA0 = sm + SW_F;
    float* sA1 = sA0 + SA_F;
    uint32_t sA0u = (uint32_t)__cvta_generic_to_shared(sA0);
    uint32_t sA1u = (uint32_t)__cvta_generic_to_shared(sA1);

    const float* __restrict__ Whh = g_Whh[LAYER];

    int tid = threadIdx.x, w = tid >> 5, lane = tid & 31, q = lane & 3, gq = lane >> 2;
    int wm = w & 1, wn = w >> 1;
    int bi = blockIdx.x & 3, ni = blockIdx.x >> 2;
    int b0 = bi * 64, n0 = ni * 64;
    int odd = q & 1;

    unsigned* mycnt = &g_cnt[LAYER][bi][ni >> 3];
    const unsigned* cnt_b = g_cnt[LAYER][bi];

    // epilogue ownership: even lanes handle row gq, odd lanes row gq+8;
    // unit within warp tile = wn*8 + (q>>1) + nt*2
    int rbase = wm * 32 + gq + odd * 8;        // + mt*16
    int jloc  = wn * 8 + (q >> 1);             // + nt*2
    int hbase = (b0 + rbase) * HH + ni * 16 + jloc;
    int xoff = n0 + 4 * jloc;                  // + nt*8

    // resident W slice: 64 rows x 512 K
    for (int i = tid; i < 64 * 128; i += 128) {
        int row = i >> 7, c4 = i & 127;
        *reinterpret_cast<float4*>(&sW[row * WPAD + c4 * 4]) =
            *reinterpret_cast<const float4*>(Whh + (long)(n0 + row) * HH + c4 * 4);
    }

    // zero-init my h slice (counts as production #1) + register c
    float c_reg[8];
#pragma unroll
    for (int mt = 0; mt < 2; mt++)
#pragma unroll
        for (int nt = 0; nt < 4; nt++) {
            c_reg[mt * 4 + nt] = 0.0f;
            g_hbuf[0][hbase + mt * 16 * HH + nt * 2] = 0.0f;
        }
    __threadfence();
    __syncthreads();
    if (tid == 0) atomicAdd(mycnt, 1u);

    for (int t = 0; t < TT; t++) {
        const float* __restrict__ hprev = g_hbuf[t & 1];
        float* __restrict__ hnew        = g_hbuf[(t + 1) & 1];
        const float* __restrict__ xp_t  = g_xproj + (size_t)t * BB * GG;
        float* __restrict__ hseq_t      = g_hseq + (size_t)t * BB * HH;
        const unsigned thr = 8u * (unsigned)(t + 1);   // 8 producers per counter + init

        // xp register prefetch (independent of h; consumed in the epilogue)
        float4 xp4[2][4];
#pragma unroll
        for (int mt = 0; mt < 2; mt++)
#pragma unroll
            for (int nt = 0; nt < 4; nt++)
                xp4[mt][nt] = *reinterpret_cast<const float4*>(
                    xp_t + (size_t)(b0 + rbase + mt * 16) * GG + xoff + nt * 8);

        float acc[2][4][4] = {};

        wait_cnt(&cnt_b[0], thr);
#pragma unroll
        for (int r = 0; r < 16; r++) {
            int idx = tid + r * 128;
            int row = idx >> 5, c4 = idx & 31;
            cpasync16(sA0u + (row * APAD + c4 * 4) * 4,
                      hprev + (size_t)(b0 + row) * HH + c4 * 4);
        }
        cpasync_commit();

#pragma unroll
        for (int ch = 0; ch < 4; ch++) {
            if (ch < 3) wait_cnt(&cnt_b[ch + 1], thr);   // detect before data wait
            cpasync_wait<0>();
            __syncthreads();
            if (ch < 3) {
                uint32_t dstu = ((ch + 1) & 1) ? sA1u : sA0u;
#pragma unroll
                for (int r = 0; r < 16; r++) {
                    int idx = tid + r * 128;
                    int row = idx >> 5, c4 = idx & 31;
                    cpasync16(dstu + (row * APAD + c4 * 4) * 4,
                              hprev + (size_t)(b0 + row) * HH + (ch + 1) * 128 + c4 * 4);
                }
                cpasync_commit();
            }
            const float* cA = ((ch & 1) ? sA1 : sA0) + (wm * 32) * APAD;
            const float* cW = sW + (wn * 32) * WPAD + ch * 128;
#pragma unroll 4
            for (int ks = 0; ks < 16; ks++) {
                int k2 = ks * 8 + 2 * q;
                float2 aL0 = *reinterpret_cast<const float2*>(cA + gq * APAD + k2);
                float2 aH0 = *reinterpret_cast<const float2*>(cA + (gq + 8) * APAD + k2);
                float2 aL1 = *reinterpret_cast<const float2*>(cA + (16 + gq) * APAD + k2);
                float2 aH1 = *reinterpret_cast<const float2*>(cA + (24 + gq) * APAD + k2);
#pragma unroll
                for (int nt = 0; nt < 4; nt++) {
                    float2 bf = *reinterpret_cast<const float2*>(cW + (nt * 8 + gq) * WPAD + k2);
                    mma_tf32(acc[0][nt], aL0.x, aH0.x, aL0.y, aH0.y, bf.x, bf.y);
                    mma_tf32(acc[1][nt], aL1.x, aH1.x, aL1.y, aH1.y, bf.x, bf.y);
                }
            }
        }

        // register epilogue: gather (i,f,g,o) per thread with 4 shuffles
        float hv[8];
#pragma unroll
        for (int mt = 0; mt < 2; mt++)
#pragma unroll
            for (int nt = 0; nt < 4; nt++) {
                float* a = acc[mt][nt];
                float p0 = __shfl_xor_sync(0xFFFFFFFFu, a[0], 1);
                float p1 = __shfl_xor_sync(0xFFFFFFFFu, a[1], 1);
                float p2 = __shfl_xor_sync(0xFFFFFFFFu, a[2], 1);
                float p3 = __shfl_xor_sync(0xFFFFFFFFu, a[3], 1);
                float gi = odd ? p2 : a[0];
                float gf = odd ? p3 : a[1];
                float gg = odd ? a[2] : p0;
                float go = odd ? a[3] : p1;
                float4 xp = xp4[mt][nt];
                float I = fsigm(gi + xp.x);
                float F = fsigm(gf + xp.y);
                float G = ftanh(gg + xp.z);
                float O = fsigm(go + xp.w);
                int s = mt * 4 + nt;
                float cv = F * c_reg[s] + I * G;
                float h = tf32f(O * ftanh(cv));
                c_reg[s] = cv;
                hv[s] = h;
                hnew[hbase + mt * 16 * HH + nt * 2] = h;
            }

        // publish: fence covers hnew only (hseq stores deferred past the signal)
        __threadfence();
        __syncthreads();
        if (tid == 0) atomicAdd(mycnt, 1u);

        if (LAYER == 0) {
#pragma unroll
            for (int mt = 0; mt < 2; mt++)
#pragma unroll
                for (int nt = 0; nt < 4; nt++)
                    hseq_t[hbase + mt * 16 * HH + nt * 2] = hv[mt * 4 + nt];
        }
    }
}

// ---------------- output head ----------------
__global__ void final_kernel(const float* __restrict__ Wout, const float* __restrict__ bout,
                             float* __restrict__ out) {
    __shared__ float sw[HH];
    int tid = threadIdx.x;
    for (int i = tid; i < HH; i += 256) sw[i] = Wout[i];
    __syncthreads();
    const float* h = g_hbuf[0];   // TT even -> last h in buffer 0
    float s = bout[0];
#pragma unroll 4
    for (int j = 0; j < HH; j++) {
        float v = h[tid * HH + j];
        v = v > 0.0f ? v : 0.0f;
        s += v * sw[j];
    }
    out[tid] = s;
}

// ---------------- launch ----------------
extern "C" void kernel_launch(void* const* d_in, const int* in_sizes, int n_in,
                              void* d_out, int out_size) {
    (void)in_sizes; (void)n_in; (void)out_size;
    const float* x    = (const float*)d_in[0];
    const float* Wih0 = (const float*)d_in[1];
    const float* Whh0 = (const float*)d_in[2];
    const float* bih0 = (const float*)d_in[3];
    const float* bhh0 = (const float*)d_in[4];
    const float* Wih1 = (const float*)d_in[5];
    const float* Whh1 = (const float*)d_in[6];
    const float* bih1 = (const float*)d_in[7];
    const float* bhh1 = (const float*)d_in[8];
    const float* Wout = (const float*)d_in[9];
    const float* bout = (const float*)d_in[10];
    float* out = (float*)d_out;

    cudaFuncSetAttribute(scan_kernel<0>, cudaFuncAttributeMaxDynamicSharedMemorySize, SMEM_SCAN);
    cudaFuncSetAttribute(scan_kernel<1>, cudaFuncAttributeMaxDynamicSharedMemorySize, SMEM_SCAN);
    cudaFuncSetAttribute(inproj2_kernel, cudaFuncAttributeMaxDynamicSharedMemorySize, IP2_SMEM);

    prep_kernel<<<1024, 256>>>(Wih0, Whh0, bih0, bhh0, Wih1, Whh1, bih1, bhh1);

    inproj0_kernel<<<dim3(2048, 32), 256>>>(x);
    scan_kernel<0><<<NCTA, 128, SMEM_SCAN>>>();

    inproj2_kernel<<<dim3(16, 1024), 256, IP2_SMEM>>>();
    scan_kernel<1><<<NCTA, 128, SMEM_SCAN>>>();

    final_kernel<<<1, 256>>>(Wout, bout, out);
}

// round 7
// speedup vs baseline: 1.0623x; 1.0623x over previous
#include <cuda_runtime.h>
#include <cstdint>

#define BB 256
#define TT 512
#define IND 64
#define HH 512
#define GG 2048   // 4*H
#define NCTA 128

// ---------------- device scratch ----------------
__device__ float g_xproj[(size_t)TT * BB * GG];
__device__ float g_hseq [(size_t)TT * BB * HH];
__device__ float g_hbuf [2][BB * HH];
__device__ float g_Whh  [2][GG * HH];     // gate-interleaved rows, tf32-rounded
__device__ float g_Wih0 [GG * IND];
__device__ float g_Wih1 [GG * HH];
__device__ float g_bias [2][GG];
__device__ unsigned g_cnt[2][4][4];       // [layer][batch-tile][k-chunk] monotonic counters

// ---------------- helpers ----------------
__device__ __forceinline__ float tf32f(float x) {
    uint32_t u;
    asm("cvt.rna.tf32.f32 %0, %1;" : "=r"(u) : "f"(x));
    return __uint_as_float(u);
}

// pair-fragment mma: thread q supplies k-lanes (q, q+4); we feed it the
// adjacent pair (k0+2q, k0+2q+1) from BOTH operands -> dot product unchanged.
__device__ __forceinline__ void mma_tf32(float* c,
                                         float a0, float a1, float a2, float a3,
                                         float b0, float b1) {
    asm volatile(
        "mma.sync.aligned.m16n8k8.row.col.f32.tf32.tf32.f32 "
        "{%0,%1,%2,%3}, {%4,%5,%6,%7}, {%8,%9}, {%0,%1,%2,%3};\n"
        : "+f"(c[0]), "+f"(c[1]), "+f"(c[2]), "+f"(c[3])
        : "r"(__float_as_uint(a0)), "r"(__float_as_uint(a1)),
          "r"(__float_as_uint(a2)), "r"(__float_as_uint(a3)),
          "r"(__float_as_uint(b0)), "r"(__float_as_uint(b1)));
}

__device__ __forceinline__ float fsigm(float x) {
    return __fdividef(1.0f, 1.0f + __expf(-x));
}
__device__ __forceinline__ float ftanh(float x) {
    return 2.0f * __fdividef(1.0f, 1.0f + __expf(-2.0f * x)) - 1.0f;
}

__device__ __forceinline__ void cpasync16(uint32_t saddr, const void* g) {
    asm volatile("cp.async.cg.shared.global [%0], [%1], 16;\n" :: "r"(saddr), "l"(g));
}
__device__ __forceinline__ void cpasync_commit() {
    asm volatile("cp.async.commit_group;\n");
}
template <int N> __device__ __forceinline__ void cpasync_wait() {
    asm volatile("cp.async.wait_group %0;\n" :: "n"(N) : "memory");
}

__device__ __forceinline__ unsigned ld_acq(const unsigned* p) {
    unsigned v;
    asm volatile("ld.acquire.gpu.global.u32 %0, [%1];" : "=r"(v) : "l"(p) : "memory");
    return v;
}

__device__ __forceinline__ void wait_cnt(const unsigned* p, unsigned thr) {
    if (ld_acq(p) >= thr) return;
    while (ld_acq(p) < thr) __nanosleep(32);
}

// ---------------- weight permute (gate interleave) + tf32 pre-round ----------------
__global__ void prep_kernel(const float* __restrict__ Wih0, const float* __restrict__ Whh0,
                            const float* __restrict__ bih0, const float* __restrict__ bhh0,
                            const float* __restrict__ Wih1, const float* __restrict__ Whh1,
                            const float* __restrict__ bih1, const float* __restrict__ bhh1) {
    int stride = gridDim.x * blockDim.x;
    int tid = blockIdx.x * blockDim.x + threadIdx.x;
    if (blockIdx.x == 0 && threadIdx.x < 32) {
        ((unsigned*)g_cnt)[threadIdx.x] = 0u;   // reset counters every replay
    }
    for (int i = tid; i < GG * HH; i += stride) {
        int orow = i / HH, k = i - orow * HH;
        int j = orow >> 2, gate = orow & 3;
        int src = (gate * HH + j) * HH + k;
        g_Whh[0][i] = tf32f(Whh0[src]);
        g_Whh[1][i] = tf32f(Whh1[src]);
        g_Wih1[i]   = tf32f(Wih1[src]);
    }
    for (int i = tid; i < GG * IND; i += stride) {
        int orow = i / IND, k = i - orow * IND;
        int j = orow >> 2, gate = orow & 3;
        g_Wih0[i] = tf32f(Wih0[(gate * HH + j) * IND + k]);
    }
    for (int i = tid; i < GG; i += stride) {
        int j = i >> 2, gate = i & 3;
        int src = gate * HH + j;
        g_bias[0][i] = bih0[src] + bhh0[src];
        g_bias[1][i] = bih1[src] + bhh1[src];
    }
}

// ---------------- layer-0 input projection (K=64) ----------------
#define KC 64
__global__ void __launch_bounds__(256)
inproj0_kernel(const float* __restrict__ x) {
    __shared__ float sA[64][KC + 4];
    __shared__ float sB[64][KC + 4];

    const float* __restrict__ W    = g_Wih0;
    const float* __restrict__ bias = g_bias[0];

    int tid = threadIdx.x;
    int m0 = blockIdx.x * 64;
    int n0 = blockIdx.y * 64;
    int t  = m0 >> 8;
    int b0 = m0 & 255;
    const float* Abase = x + (size_t)b0 * TT * IND + (size_t)t * IND;

    int w = tid >> 5, lane = tid & 31, q = lane & 3, gq = lane >> 2;
    int wm = w & 3, wn = w >> 2;

    float acc[4][4] = {};

#pragma unroll
    for (int r = 0; r < 4; r++) {
        int idx = tid + r * 256;
        int row = idx >> 4;
        int c4  = idx & 15;
        float4 v = *reinterpret_cast<const float4*>(Abase + (size_t)row * TT * IND + c4 * 4);
        v.x = tf32f(v.x); v.y = tf32f(v.y); v.z = tf32f(v.z); v.w = tf32f(v.w);
        *reinterpret_cast<float4*>(&sA[row][c4 * 4]) = v;
        float4 wv = *reinterpret_cast<const float4*>(W + (long)(n0 + row) * IND + c4 * 4);
        *reinterpret_cast<float4*>(&sB[row][c4 * 4]) = wv;
    }
    __syncthreads();
#pragma unroll
    for (int ks = 0; ks < KC / 8; ks++) {
        int k0 = ks * 8;
        float a0 = sA[wm * 16 + gq    ][k0 + q];
        float a1 = sA[wm * 16 + gq + 8][k0 + q];
        float a2 = sA[wm * 16 + gq    ][k0 + q + 4];
        float a3 = sA[wm * 16 + gq + 8][k0 + q + 4];
#pragma unroll
        for (int nt = 0; nt < 4; nt++) {
            int n = wn * 32 + nt * 8 + gq;
            mma_tf32(acc[nt], a0, a1, a2, a3, sB[n][k0 + q], sB[n][k0 + q + 4]);
        }
    }

#pragma unroll
    for (int nt = 0; nt < 4; nt++) {
        int col = n0 + wn * 32 + nt * 8 + q * 2;
        float bv0 = bias[col], bv1 = bias[col + 1];
        int row = m0 + wm * 16 + gq;
        *reinterpret_cast<float2*>(g_xproj + (size_t)row * GG + col) =
            make_float2(acc[nt][0] + bv0, acc[nt][1] + bv1);
        *reinterpret_cast<float2*>(g_xproj + (size_t)(row + 8) * GG + col) =
            make_float2(acc[nt][2] + bv0, acc[nt][3] + bv1);
    }
}

// ---------------- layer-1 input projection: 128x128 CTA, 64x32 warps ----------------
#define IP_APAD 72
#define IP_TILEF (128 * IP_APAD)
#define IP2_SMEM (4 * IP_TILEF * 4)

__global__ void __launch_bounds__(256, 1)
inproj2_kernel() {
    extern __shared__ float sm[];
    float* sA[2] = { sm,                sm + IP_TILEF };
    float* sB[2] = { sm + 2 * IP_TILEF, sm + 3 * IP_TILEF };
    uint32_t sAu[2], sBu[2];
#pragma unroll
    for (int i = 0; i < 2; i++) {
        sAu[i] = (uint32_t)__cvta_generic_to_shared(sA[i]);
        sBu[i] = (uint32_t)__cvta_generic_to_shared(sB[i]);
    }

    int tid = threadIdx.x, w = tid >> 5, lane = tid & 31, q = lane & 3, gq = lane >> 2;
    int wm = w & 1, wn = w >> 1;
    int n0 = blockIdx.x * 128;
    long m0 = (long)blockIdx.y * 128;
    const float* Ab = g_hseq + m0 * HH;
    const float* Bb = g_Wih1 + (long)n0 * HH;

    float acc[4][4][4] = {};

#pragma unroll
    for (int r = 0; r < 8; r++) {
        int idx = tid + r * 256;
        int row = idx >> 4, c4 = idx & 15;
        cpasync16(sAu[0] + (row * IP_APAD + c4 * 4) * 4, Ab + (long)row * HH + c4 * 4);
        cpasync16(sBu[0] + (row * IP_APAD + c4 * 4) * 4, Bb + (long)row * HH + c4 * 4);
    }
    cpasync_commit();

    for (int ch = 0; ch < 8; ch++) {
        cpasync_wait<0>();
        __syncthreads();
        if (ch < 7) {
            int bi = (ch + 1) & 1;
#pragma unroll
            for (int r = 0; r < 8; r++) {
                int idx = tid + r * 256;
                int row = idx >> 4, c4 = idx & 15;
                cpasync16(sAu[bi] + (row * IP_APAD + c4 * 4) * 4,
                          Ab + (long)row * HH + (ch + 1) * 64 + c4 * 4);
                cpasync16(sBu[bi] + (row * IP_APAD + c4 * 4) * 4,
                          Bb + (long)row * HH + (ch + 1) * 64 + c4 * 4);
            }
            cpasync_commit();
        }
        const float* cA = sA[ch & 1] + (wm * 64) * IP_APAD;
        const float* cB = sB[ch & 1] + (wn * 32) * IP_APAD;
#pragma unroll
        for (int ks = 0; ks < 8; ks++) {
            int k2 = ks * 8 + 2 * q;
            float2 aL[4], aH[4];
#pragma unroll
            for (int mt = 0; mt < 4; mt++) {
                aL[mt] = *reinterpret_cast<const float2*>(cA + (mt * 16 + gq    ) * IP_APAD + k2);
                aH[mt] = *reinterpret_cast<const float2*>(cA + (mt * 16 + gq + 8) * IP_APAD + k2);
            }
#pragma unroll
            for (int nt = 0; nt < 4; nt++) {
                float2 bf = *reinterpret_cast<const float2*>(cB + (nt * 8 + gq) * IP_APAD + k2);
#pragma unroll
                for (int mt = 0; mt < 4; mt++)
                    mma_tf32(acc[mt][nt], aL[mt].x, aH[mt].x, aL[mt].y, aH[mt].y, bf.x, bf.y);
            }
        }
    }

#pragma unroll
    for (int nt = 0; nt < 4; nt++) {
        int col = n0 + wn * 32 + nt * 8 + q * 2;
        float bv0 = g_bias[1][col], bv1 = g_bias[1][col + 1];
#pragma unroll
        for (int mt = 0; mt < 4; mt++) {
            long row = m0 + wm * 64 + mt * 16 + gq;
            *reinterpret_cast<float2*>(g_xproj + row * GG + col) =
                make_float2(acc[mt][nt][0] + bv0, acc[mt][nt][1] + bv1);
            *reinterpret_cast<float2*>(g_xproj + (row + 8) * GG + col) =
                make_float2(acc[mt][nt][2] + bv0, acc[mt][nt][3] + bv1);
        }
    }
}

// ---------------- persistent LSTM scan: 256 threads, 8 warps of 32x16 tiles ----------------
// CTA (bi, ni): batch tile b0=64*bi, gate-column tile n0=64*ni (hidden j0=16*ni).
// Counters: g_cnt[L][bi][g] incremented by the 8 CTAs with ni in [8g, 8g+8);
// init counts as the first signal, so consumer threshold for step t is 8*(t+1).
#define WPAD 520
#define APAD 136
#define XPAD 68
#define GPAD 72
#define SW_F (64 * WPAD)
#define SA_F (64 * APAD)
#define XP_F (64 * XPAD)
#define SMEM_SCAN ((SW_F + 2 * SA_F + XP_F) * 4)

template <int LAYER>
__global__ void __launch_bounds__(256, 1)
scan_kernel() {
    extern __shared__ float sm[];
    float* sW  = sm;
    float* sA0 = sm + SW_F;
    float* sA1 = sA0 + SA_F;
    float* sXP = sA1 + SA_F;
    uint32_t sA0u = (uint32_t)__cvta_generic_to_shared(sA0);
    uint32_t sA1u = (uint32_t)__cvta_generic_to_shared(sA1);
    uint32_t sXPu = (uint32_t)__cvta_generic_to_shared(sXP);

    const float* __restrict__ Whh = g_Whh[LAYER];

    int tid = threadIdx.x, w = tid >> 5, lane = tid & 31, q = lane & 3, gq = lane >> 2;
    int wm = w & 1, wn = w >> 1;             // 8 warps: wm in {0,1} (32 rows), wn in 0..3 (16 cols)
    int bi = blockIdx.x & 3, ni = blockIdx.x >> 2;
    int b0 = bi * 64, n0 = ni * 64, j0 = ni * 16;

    unsigned* mycnt = &g_cnt[LAYER][bi][ni >> 3];
    const unsigned* cnt_b = g_cnt[LAYER][bi];

    // resident W slice: 64 rows x 512 K
    for (int i = tid; i < 64 * 128; i += 256) {
        int row = i >> 7, c4 = i & 127;
        *reinterpret_cast<float4*>(&sW[row * WPAD + c4 * 4]) =
            *reinterpret_cast<const float4*>(Whh + (long)(n0 + row) * HH + c4 * 4);
    }

    // zero-init my h slice (counts as production #1) + register c (4 units/thread)
    float c_reg[4];
#pragma unroll
    for (int s = 0; s < 4; s++) {
        c_reg[s] = 0.0f;
        int idx = tid + s * 256;
        int b = idx >> 4, j = idx & 15;
        g_hbuf[0][(b0 + b) * HH + j0 + j] = 0.0f;
    }
    __threadfence();
    __syncthreads();
    if (tid == 0) atomicAdd(mycnt, 1u);

    for (int t = 0; t < TT; t++) {
        const float* __restrict__ hprev = g_hbuf[t & 1];
        float* __restrict__ hnew        = g_hbuf[(t + 1) & 1];
        const float* __restrict__ xp_t  = g_xproj + (size_t)t * BB * GG;
        float* __restrict__ hseq_t      = g_hseq + (size_t)t * BB * HH;
        const unsigned thr = 8u * (unsigned)(t + 1);   // 8 producers per counter + init

        float acc[2][2][4] = {};

        // xp tile prefetch (independent of h) into sXP
#pragma unroll
        for (int r = 0; r < 4; r++) {
            int idx = tid + r * 256;
            int row = idx >> 4, c4 = idx & 15;
            cpasync16(sXPu + (row * XPAD + c4 * 4) * 4,
                      xp_t + (size_t)(b0 + row) * GG + n0 + c4 * 4);
        }
        wait_cnt(&cnt_b[0], thr);
#pragma unroll
        for (int r = 0; r < 8; r++) {
            int idx = tid + r * 256;
            int row = idx >> 5, c4 = idx & 31;
            cpasync16(sA0u + (row * APAD + c4 * 4) * 4,
                      hprev + (size_t)(b0 + row) * HH + c4 * 4);
        }
        cpasync_commit();

#pragma unroll
        for (int ch = 0; ch < 4; ch++) {
            if (ch < 3) wait_cnt(&cnt_b[ch + 1], thr);   // detect before data wait
            cpasync_wait<0>();
            __syncthreads();
            if (ch < 3) {
                uint32_t dstu = ((ch + 1) & 1) ? sA1u : sA0u;
#pragma unroll
                for (int r = 0; r < 8; r++) {
                    int idx = tid + r * 256;
                    int row = idx >> 5, c4 = idx & 31;
                    cpasync16(dstu + (row * APAD + c4 * 4) * 4,
                              hprev + (size_t)(b0 + row) * HH + (ch + 1) * 128 + c4 * 4);
                }
                cpasync_commit();
            }
            const float* cA = ((ch & 1) ? sA1 : sA0) + (wm * 32) * APAD;
            const float* cW = sW + (wn * 16) * WPAD + ch * 128;
#pragma unroll 4
            for (int ks = 0; ks < 16; ks++) {
                int k2 = ks * 8 + 2 * q;
                float2 aL0 = *reinterpret_cast<const float2*>(cA + gq * APAD + k2);
                float2 aH0 = *reinterpret_cast<const float2*>(cA + (gq + 8) * APAD + k2);
                float2 aL1 = *reinterpret_cast<const float2*>(cA + (16 + gq) * APAD + k2);
                float2 aH1 = *reinterpret_cast<const float2*>(cA + (24 + gq) * APAD + k2);
#pragma unroll
                for (int nt = 0; nt < 2; nt++) {
                    float2 bf = *reinterpret_cast<const float2*>(cW + (nt * 8 + gq) * WPAD + k2);
                    mma_tf32(acc[0][nt], aL0.x, aH0.x, aL0.y, aH0.y, bf.x, bf.y);
                    mma_tf32(acc[1][nt], aL1.x, aH1.x, aL1.y, aH1.y, bf.x, bf.y);
                }
            }
        }

        // stage gate tile (i,f,g,o quadruples) into sA0 region
        float* Gm = sA0;
#pragma unroll
        for (int mt = 0; mt < 2; mt++)
#pragma unroll
            for (int nt = 0; nt < 2; nt++) {
                int row = wm * 32 + mt * 16 + gq;
                int col = wn * 16 + nt * 8 + q * 2;
                *reinterpret_cast<float2*>(&Gm[row * GPAD + col]) =
                    make_float2(acc[mt][nt][0], acc[mt][nt][1]);
                *reinterpret_cast<float2*>(&Gm[(row + 8) * GPAD + col]) =
                    make_float2(acc[mt][nt][2], acc[mt][nt][3]);
            }
        __syncthreads();

#pragma unroll
        for (int s = 0; s < 4; s++) {
            int idx = tid + s * 256;
            int b = idx >> 4, j = idx & 15;
            float4 gm = *reinterpret_cast<float4*>(&Gm[b * GPAD + j * 4]);
            float4 xp = *reinterpret_cast<float4*>(&sXP[b * XPAD + j * 4]);
            float ig = fsigm(gm.x + xp.x);
            float fg = fsigm(gm.y + xp.y);
            float gg = ftanh(gm.z + xp.z);
            float og = fsigm(gm.w + xp.w);
            float c = fg * c_reg[s] + ig * gg;
            float h = tf32f(og * ftanh(c));
            c_reg[s] = c;
            int ci = (b0 + b) * HH + j0 + j;
            hnew[ci] = h;
            if (LAYER == 0) hseq_t[ci] = h;
        }

        // publish
        __threadfence();
        __syncthreads();
        if (tid == 0) atomicAdd(mycnt, 1u);
    }
}

// ---------------- output head ----------------
__global__ void final_kernel(const float* __restrict__ Wout, const float* __restrict__ bout,
                             float* __restrict__ out) {
    __shared__ float sw[HH];
    int tid = threadIdx.x;
    for (int i = tid; i < HH; i += 256) sw[i] = Wout[i];
    __syncthreads();
    const float* h = g_hbuf[0];   // TT even -> last h in buffer 0
    float s = bout[0];
#pragma unroll 4
    for (int j = 0; j < HH; j++) {
        float v = h[tid * HH + j];
        v = v > 0.0f ? v : 0.0f;
        s += v * sw[j];
    }
    out[tid] = s;
}

// ---------------- launch ----------------
extern "C" void kernel_launch(void* const* d_in, const int* in_sizes, int n_in,
                              void* d_out, int out_size) {
    (void)in_sizes; (void)n_in; (void)out_size;
    const float* x    = (const float*)d_in[0];
    const float* Wih0 = (const float*)d_in[1];
    const float* Whh0 = (const float*)d_in[2];
    const float* bih0 = (const float*)d_in[3];
    const float* bhh0 = (const float*)d_in[4];
    const float* Wih1 = (const float*)d_in[5];
    const float* Whh1 = (const float*)d_in[6];
    const float* bih1 = (const float*)d_in[7];
    const float* bhh1 = (const float*)d_in[8];
    const float* Wout = (const float*)d_in[9];
    const float* bout = (const float*)d_in[10];
    float* out = (float*)d_out;

    cudaFuncSetAttribute(scan_kernel<0>, cudaFuncAttributeMaxDynamicSharedMemorySize, SMEM_SCAN);
    cudaFuncSetAttribute(scan_kernel<1>, cudaFuncAttributeMaxDynamicSharedMemorySize, SMEM_SCAN);
    cudaFuncSetAttribute(inproj2_kernel, cudaFuncAttributeMaxDynamicSharedMemorySize, IP2_SMEM);

    prep_kernel<<<1024, 256>>>(Wih0, Whh0, bih0, bhh0, Wih1, Whh1, bih1, bhh1);

    inproj0_kernel<<<dim3(2048, 32), 256>>>(x);
    scan_kernel<0><<<NCTA, 256, SMEM_SCAN>>>();

    inproj2_kernel<<<dim3(16, 1024), 256, IP2_SMEM>>>();
    scan_kernel<1><<<NCTA, 256, SMEM_SCAN>>>();

    final_kernel<<<1, 256>>>(Wout, bout, out);
}